// round 8
// baseline (speedup 1.0000x reference)
#include <cuda_runtime.h>
#include <math.h>
#include <stdint.h>

#define BS    512
#define LNUM  68
#define IMG   224
#define RS    7
#define R2    49
#define LL    (LNUM * LNUM)     // 4624
#define NTHR  512               // 16 warps
#define NWARP 16
#define FULLM 0xFFFFFFFFu
#define NGRP  ((LL - 4) / 4)    // 1155 float4 store groups per batch

__device__ double   g_sumL = 0.0;
__device__ double   g_sumM = 0.0;
__device__ unsigned g_done = 0u;

__device__ __forceinline__ uint32_t smem_u32(const void* p) {
    return (uint32_t)__cvta_generic_to_shared(p);
}

// linspace(-3.5,3.5,7)[k] / 224 * 2 — identical op order to the reference.
__device__ __forceinline__ float xval(int k) {
    float x = -3.5f + (float)k * (7.0f / 6.0f);
    if (k == RS - 1) x = 3.5f;
    return x / 224.0f * 2.0f;
}

// One region sample; exact replica of the reference's grid_sample-nearest
// arithmetic (rintf == jnp.round, half-even).
__device__ __forceinline__ float sample(const float* __restrict__ dimg,
                                        float fx, float fy, float cx, float cy)
{
    float gy = fy + cy;
    float gx = fx + cx;
    float iy = ((gy + 1.0f) * 224.0f - 1.0f) * 0.5f;
    float ix = ((gx + 1.0f) * 224.0f - 1.0f) * 0.5f;
    int yi = (int)rintf(iy);
    int xi = (int)rintf(ix);
    bool v = (yi >= 0) & (yi < IMG) & (xi >= 0) & (xi < IMG);
    int yc = min(max(yi, 0), IMG - 1);
    int xc = min(max(xi, 0), IMG - 1);
    float val = __ldg(dimg + yc * IMG + xc);
    return v ? val : 0.0f;
}

// One bitonic stage for a 64-element warp sort (id(v0)=lane, id(v1)=lane+32).
template<int K, int D>
__device__ __forceinline__ void bstage(float& v0, float& v1, int lane)
{
    bool low = ((lane & D) == 0);                 // id & D == 0 (D < 32)
    bool up0 = ((lane & (K & 31)) == 0) || (K >= 32);   // (id&K)==0 for id=lane
    bool up1 = (K <= 16) ? up0 : (K == 64);             // for id=lane+32
    float w0 = __shfl_xor_sync(FULLM, v0, D);
    v0 = (low == up0) ? fminf(v0, w0) : fmaxf(v0, w0);
    float w1 = __shfl_xor_sync(FULLM, v1, D);
    v1 = (low == up1) ? fminf(v1, w1) : fmaxf(v1, w1);
}

// Full ascending sort of 64 values (49 real + 15 INF pads), then extract the
// reference's region median: rank mi = (clamp(count(v<=THR),1,48)+48)/2.
__device__ __forceinline__ float region_median_sorted(float v0, float v1, int lane)
{
    bstage<2, 1>(v0, v1, lane);
    bstage<4, 2>(v0, v1, lane);  bstage<4, 1>(v0, v1, lane);
    bstage<8, 4>(v0, v1, lane);  bstage<8, 2>(v0, v1, lane);  bstage<8, 1>(v0, v1, lane);
    bstage<16, 8>(v0, v1, lane); bstage<16, 4>(v0, v1, lane);
    bstage<16, 2>(v0, v1, lane); bstage<16, 1>(v0, v1, lane);
    bstage<32, 16>(v0, v1, lane); bstage<32, 8>(v0, v1, lane);
    bstage<32, 4>(v0, v1, lane);  bstage<32, 2>(v0, v1, lane);
    bstage<32, 1>(v0, v1, lane);
    { float lo = fminf(v0, v1), hi = fmaxf(v0, v1); v0 = lo; v1 = hi; }  // K=64,D=32
    bstage<64, 16>(v0, v1, lane); bstage<64, 8>(v0, v1, lane);
    bstage<64, 4>(v0, v1, lane);  bstage<64, 2>(v0, v1, lane);
    bstage<64, 1>(v0, v1, lane);

    unsigned c0 = __ballot_sync(FULLM, v0 <= 1e-4f);
    unsigned c1 = __ballot_sync(FULLM, v1 <= 1e-4f);   // INF pads never match
    int k  = __popc(c0) + __popc(c1);
    int st = min(max(k, 1), R2 - 1);
    int mi = (st + R2 - 1) >> 1;                        // in [24,48]
    float r0 = __shfl_sync(FULLM, v0, mi);              // srcLane mod 32
    float r1 = __shfl_sync(FULLM, v1, mi);
    return (mi < 32) ? r0 : r1;
}

__global__ __launch_bounds__(NTHR, 4) void fused_kernel(
    const float* __restrict__ rel,
    const float* __restrict__ depth,
    const float* __restrict__ lm,
    const float* __restrict__ sf,
    const float* __restrict__ bbox,
    float* __restrict__ out)
{
    __shared__ float  s_rel[LL];             // staged via cp.async.bulk
    __shared__ float  smed[LNUM];            // raw region medians
    __shared__ float2 s_mm[LNUM];            // (med*500, mask)
    __shared__ float  s_mom;
    __shared__ int    s_cnt[3];
    __shared__ double redL[NWARP];
    __shared__ bool   s_last;
    __shared__ __align__(8) unsigned long long s_mbar;

    int b    = blockIdx.x;
    int tid  = threadIdx.x;
    int wid  = tid >> 5;
    int lane = tid & 31;

    const size_t base = (size_t)b * LL;
    const float* relb = rel + base;

    // ---- phase 0: bulk copy rel[batch] -> smem (overlaps phase 1/2) ----
    uint32_t mb = smem_u32(&s_mbar);
    if (tid == 0) {
        asm volatile("mbarrier.init.shared.b64 [%0], 1;" :: "r"(mb) : "memory");
        asm volatile("fence.proxy.async.shared::cta;" ::: "memory");
        asm volatile("mbarrier.arrive.expect_tx.shared.b64 _, [%0], %1;"
                     :: "r"(mb), "r"((uint32_t)(LL * 4)) : "memory");
        asm volatile("cp.async.bulk.shared::cta.global.mbarrier::complete_tx::bytes "
                     "[%0], [%1], %2, [%3];"
                     :: "r"(smem_u32(s_rel)), "l"(relb),
                        "r"((uint32_t)(LL * 4)), "r"(mb) : "memory");
    }

    // ---- hoisted per-lane slot constants ----
    int p0 = lane / RS,  q0 = lane - RS * p0;
    int s1 = lane + 32;
    int p1 = s1 / RS,    q1 = s1 - RS * p1;
    float cy0 = xval(p0), cx0 = xval(q0);
    float cy1 = xval(p1), cx1 = xval(q1);
    bool  hi_ok = (lane < 17);

    float sf0 = sf[b * 2 + 0], sf1 = sf[b * 2 + 1];
    float bx  = bbox[b * 4 + 0], by = bbox[b * 4 + 1];
    const float* dimg = depth + (size_t)b * IMG * IMG;
    const float  INF  = __int_as_float(0x7f800000);

    // ---- phase 1: region medians; warp w -> landmarks 4w..4w+3 (+64+w if w<4)
    int nl = (wid < 4) ? 5 : 4;
#define LM_IDX(i) (((i) < 4) ? (wid * 4 + (i)) : (64 + wid))

    float v0, v1;
    {   // prefetch landmark 0
        int l = LM_IDX(0);
        float2 lxy = *reinterpret_cast<const float2*>(lm + ((size_t)b * LNUM + l) * 2);
        float fx = (lxy.x - bx) * sf0 / 224.0f * 2.0f - 1.0f;
        float fy = (lxy.y - by) * sf1 / 224.0f * 2.0f - 1.0f;
        v0 = sample(dimg, fx, fy, cx0, cy0);
        v1 = hi_ok ? sample(dimg, fx, fy, cx1, cy1) : INF;
    }
    for (int i = 0; i < nl; i++) {
        float nv0 = 0.0f, nv1 = INF;
        if (i + 1 < nl) {                    // prefetch next while sorting
            int l = LM_IDX(i + 1);
            float2 lxy = *reinterpret_cast<const float2*>(lm + ((size_t)b * LNUM + l) * 2);
            float fx = (lxy.x - bx) * sf0 / 224.0f * 2.0f - 1.0f;
            float fy = (lxy.y - by) * sf1 / 224.0f * 2.0f - 1.0f;
            nv0 = sample(dimg, fx, fy, cx0, cy0);
            nv1 = hi_ok ? sample(dimg, fx, fy, cx1, cy1) : INF;
        }
        float med = region_median_sorted(v0, v1, lane);
        if (lane == 0) smed[LM_IDX(i)] = med;
        v0 = nv0; v1 = nv1;
    }
#undef LM_IDX
    __syncthreads();

    // ---- phase 2: lower median-of-medians (rank 33) + mask + count ----
    float vraw = 0.0f;
    if (tid < LNUM) {
        vraw = smed[tid];
        int r = 0;
#pragma unroll 4
        for (int j = 0; j < LNUM; j++) {
            float w = smed[j];
            r += (w < vraw || (w == vraw && j < tid)) ? 1 : 0;  // stable rank
        }
        if (r == (LNUM - 1) / 2) s_mom = vraw;
    }
    __syncthreads();
    bool mbit = false;
    if (tid < LNUM) {
        mbit = fabsf(vraw - s_mom) < (90.0f / 500.0f);
        s_mm[tid] = make_float2(vraw * 500.0f, mbit ? 1.0f : 0.0f);
    }
    unsigned bal = __ballot_sync(FULLM, mbit);
    if (lane == 0 && wid < 3) s_cnt[wid] = __popc(bal);
    __syncthreads();

    // ---- wait for staged rel (TRYWAIT fast path, normally complete) ----
    {
        uint32_t done;
        do {
            asm volatile(
                "{\n\t.reg .pred p;\n\t"
                "mbarrier.try_wait.parity.acquire.cta.shared::cta.b64 p, [%1], %2;\n\t"
                "selp.b32 %0, 1, 0, p;\n\t}"
                : "=r"(done) : "r"(mb), "r"(0u) : "memory");
        } while (!done);
    }

    // ---- phase 3: pairwise diff / mask / smooth-L1, float4 stores ----
    // out[0]=loss, outd=out+1, outm=out+1+BS*LL. outd[base+e] has global float
    // index 1+base+e; base%4==0 so e≡3 (mod 4) gives 16B-aligned float4 stores.
    float* outd = out + 1;
    float* outm = out + 1 + (size_t)BS * LL;
    float accL = 0.0f;

    if (tid < 4) {                      // head e=0,1,2 and tail e=4623
        int e = (tid < 3) ? tid : (LL - 1);
        int i = e / LNUM;
        int j = e - i * LNUM;
        float2 mi2 = s_mm[i];
        float2 mj2 = s_mm[j];
        float diff = mi2.x - mj2.x;
        float mk   = mi2.y * mj2.y;
        float d    = s_rel[e] - diff;
        float ad   = fabsf(d);
        float c    = fminf(ad, 1.0f);
        float le   = c * (ad - 0.5f * c);
        outd[base + e] = diff;
        outm[base + e] = mk;
        accL += le * mk;
    }

    for (int g = tid; g < NGRP; g += NTHR) {
        int e0 = 3 + (g << 2);
        int i0 = e0 / LNUM;
        int j0 = e0 - i0 * LNUM;
        float dvv[4], mvv[4];
#pragma unroll
        for (int n = 0; n < 4; n++) {
            int jn = j0 + n;
            int wrap = (jn >= LNUM) ? 1 : 0;
            int in = i0 + wrap;
            jn -= LNUM * wrap;
            float2 mi2 = s_mm[in];
            float2 mj2 = s_mm[jn];
            float diff = mi2.x - mj2.x;
            float mk   = mi2.y * mj2.y;
            float d    = s_rel[e0 + n] - diff;
            float ad   = fabsf(d);
            float c    = fminf(ad, 1.0f);
            float le   = c * (ad - 0.5f * c);
            dvv[n] = diff;
            mvv[n] = mk;
            accL += le * mk;
        }
        *reinterpret_cast<float4*>(outd + base + e0) =
            make_float4(dvv[0], dvv[1], dvv[2], dvv[3]);
        *reinterpret_cast<float4*>(outm + base + e0) =
            make_float4(mvv[0], mvv[1], mvv[2], mvv[3]);
    }

    // ---- block reduce + global atomics + last-block finalize ----
    double dL = (double)accL;
#pragma unroll
    for (int o = 16; o > 0; o >>= 1)
        dL += __shfl_down_sync(FULLM, dL, o);
    if (lane == 0) redL[wid] = dL;
    __syncthreads();
    if (tid == 0) {
        double tL = 0.0;
#pragma unroll
        for (int w = 0; w < NWARP; w++) tL += redL[w];
        double cnt = (double)(s_cnt[0] + s_cnt[1] + s_cnt[2]);
        atomicAdd(&g_sumL, tL);
        atomicAdd(&g_sumM, cnt * cnt);      // sum_ij mi*mj == (sum m)^2
        __threadfence();
        unsigned n = atomicAdd(&g_done, 1u);
        s_last = (n == BS - 1);
    }
    __syncthreads();

    if (s_last && tid == 0) {
        __threadfence();
        double L = g_sumL, M = g_sumM;
        out[0] = (float)(L / (M + 1e-4));
        g_sumL = 0.0; g_sumM = 0.0; g_done = 0u;
    }
}

extern "C" void kernel_launch(void* const* d_in, const int* in_sizes, int n_in,
                              void* d_out, int out_size)
{
    const float* rel   = (const float*)d_in[0];   // [BS, L, L]
    const float* depth = (const float*)d_in[1];   // [BS, 1, IMG, IMG]
    const float* lm    = (const float*)d_in[2];   // [BS, L, 2]
    const float* sf    = (const float*)d_in[3];   // [BS, 2]
    const float* bbox  = (const float*)d_in[4];   // [BS, 4]
    float* out = (float*)d_out;                   // [loss | diff | mask]

    fused_kernel<<<BS, NTHR>>>(rel, depth, lm, sf, bbox, out);
}

// round 9
// speedup vs baseline: 1.3515x; 1.3515x over previous
#include <cuda_runtime.h>
#include <math.h>
#include <stdint.h>

#define BS    512
#define LNUM  68
#define IMG   224
#define RS    7
#define R2    49
#define LL    (LNUM * LNUM)     // 4624
#define NTHR  512               // 16 warps
#define NWARP 16
#define FULLM 0xFFFFFFFFu
#define NGRP  ((LL - 4) / 4)    // 1155 float4 store groups per batch

__device__ double   g_sumL = 0.0;
__device__ double   g_sumM = 0.0;
__device__ unsigned g_done = 0u;

__device__ __forceinline__ uint32_t smem_u32(const void* p) {
    return (uint32_t)__cvta_generic_to_shared(p);
}

// linspace(-3.5,3.5,7)[k] / 224 * 2 — identical op order to the reference.
__device__ __forceinline__ float xval(int k) {
    float x = -3.5f + (float)k * (7.0f / 6.0f);
    if (k == RS - 1) x = 3.5f;
    return x / 224.0f * 2.0f;
}

__global__ __launch_bounds__(NTHR, 4) void fused_kernel(
    const float* __restrict__ rel,
    const float* __restrict__ depth,
    const float* __restrict__ lm,
    const float* __restrict__ sf,
    const float* __restrict__ bbox,
    float* __restrict__ out)
{
    __shared__ float  s_rel[LL];             // staged via cp.async.bulk
    __shared__ float  smed[LNUM];            // raw region medians
    __shared__ float2 s_mm[LNUM];            // (med*500, mask)
    __shared__ float  s_mom;
    __shared__ int    s_cnt[3];
    __shared__ double redL[NWARP];
    __shared__ bool   s_last;
    __shared__ __align__(8) unsigned long long s_mbar;

    int b    = blockIdx.x;
    int tid  = threadIdx.x;
    int wid  = tid >> 5;
    int lane = tid & 31;

    const size_t base = (size_t)b * LL;
    const float* relb = rel + base;

    // ---- phase 0: bulk copy rel[batch] -> smem (overlaps phase 1/2) ----
    uint32_t mb = smem_u32(&s_mbar);
    if (tid == 0) {
        asm volatile("mbarrier.init.shared.b64 [%0], 1;" :: "r"(mb) : "memory");
        asm volatile("fence.proxy.async.shared::cta;" ::: "memory");
        asm volatile("mbarrier.arrive.expect_tx.shared.b64 _, [%0], %1;"
                     :: "r"(mb), "r"((uint32_t)(LL * 4)) : "memory");
        asm volatile("cp.async.bulk.shared::cta.global.mbarrier::complete_tx::bytes "
                     "[%0], [%1], %2, [%3];"
                     :: "r"(smem_u32(s_rel)), "l"(relb),
                        "r"((uint32_t)(LL * 4)), "r"(mb) : "memory");
    }

    // ---- phase 1: one THREAD per landmark; register sort, no warp collectives
    if (tid < LNUM) {
        float sf0 = sf[b * 2 + 0], sf1 = sf[b * 2 + 1];
        float bx  = bbox[b * 4 + 0], by = bbox[b * 4 + 1];
        const float* dimg = depth + (size_t)b * IMG * IMG;

        float2 lxy = *reinterpret_cast<const float2*>(lm + ((size_t)b * LNUM + tid) * 2);
        float fx = (lxy.x - bx) * sf0 / 224.0f * 2.0f - 1.0f;
        float fy = (lxy.y - by) * sf1 / 224.0f * 2.0f - 1.0f;

        // hoisted per-axis indices (exact reference arithmetic; rintf == jnp.round)
        int  rowoff[RS], coloff[RS];
        bool vy[RS], vx[RS];
#pragma unroll
        for (int p = 0; p < RS; p++) {
            float gy = fy + xval(p);
            float iy = ((gy + 1.0f) * 224.0f - 1.0f) * 0.5f;
            int yi = (int)rintf(iy);
            vy[p] = (yi >= 0) & (yi < IMG);
            rowoff[p] = min(max(yi, 0), IMG - 1) * IMG;
            float gx = fx + xval(p);
            float ix = ((gx + 1.0f) * 224.0f - 1.0f) * 0.5f;
            int xi = (int)rintf(ix);
            vx[p] = (xi >= 0) & (xi < IMG);
            coloff[p] = min(max(xi, 0), IMG - 1);
        }

        // gather 49 values (unrolled, MLP=49) + zero-count
        float v[R2];
        int   k = 0;
#pragma unroll
        for (int p = 0; p < RS; p++) {
#pragma unroll
            for (int q = 0; q < RS; q++) {
                float val = __ldg(dimg + rowoff[p] + coloff[q]);
                val = (vy[p] & vx[q]) ? val : 0.0f;
                v[p * RS + q] = val;
                k += (val <= 1e-4f) ? 1 : 0;
            }
        }

        // Batcher odd-even merge sort (n=64 network pruned to 49 slots).
        // All indices compile-time constants -> pure register sort.
#pragma unroll
        for (int p = 1; p < 64; p <<= 1) {
#pragma unroll
            for (int kk = p; kk >= 1; kk >>= 1) {
#pragma unroll
                for (int j = kk & (p - 1); j + kk < 64; j += 2 * kk) {
#pragma unroll
                    for (int i = 0; i < kk; i++) {
                        if (i + j + kk < R2) {
                            if ((i + j) / (2 * p) == (i + j + kk) / (2 * p)) {
                                float a  = v[i + j];
                                float bb = v[i + j + kk];
                                v[i + j]      = fminf(a, bb);
                                v[i + j + kk] = fmaxf(a, bb);
                            }
                        }
                    }
                }
            }
        }

        // median rank: mi = (clamp(k,1,48)+48)/2 in [24,48]
        int st = min(max(k, 1), R2 - 1);
        int mi = (st + R2 - 1) >> 1;
        float r = v[24];
#pragma unroll
        for (int i = 25; i < R2; i++) r = (mi >= i) ? v[i] : r;
        smed[tid] = r;
    }
    __syncthreads();

    // ---- phase 2: lower median-of-medians (rank 33) + mask + count ----
    float vraw = 0.0f;
    if (tid < LNUM) {
        vraw = smed[tid];
        int r = 0;
#pragma unroll 4
        for (int j = 0; j < LNUM; j++) {
            float w = smed[j];
            r += (w < vraw || (w == vraw && j < tid)) ? 1 : 0;  // stable rank
        }
        if (r == (LNUM - 1) / 2) s_mom = vraw;
    }
    __syncthreads();
    bool mbit = false;
    if (tid < LNUM) {
        mbit = fabsf(vraw - s_mom) < (90.0f / 500.0f);
        s_mm[tid] = make_float2(vraw * 500.0f, mbit ? 1.0f : 0.0f);
    }
    unsigned bal = __ballot_sync(FULLM, mbit);
    if (lane == 0 && wid < 3) s_cnt[wid] = __popc(bal);
    __syncthreads();

    // ---- wait for staged rel (TRYWAIT fast path, normally complete) ----
    {
        uint32_t done;
        do {
            asm volatile(
                "{\n\t.reg .pred p;\n\t"
                "mbarrier.try_wait.parity.acquire.cta.shared::cta.b64 p, [%1], %2;\n\t"
                "selp.b32 %0, 1, 0, p;\n\t}"
                : "=r"(done) : "r"(mb), "r"(0u) : "memory");
        } while (!done);
    }

    // ---- phase 3: pairwise diff / mask / smooth-L1, float4 stores ----
    // out[0]=loss, outd=out+1, outm=out+1+BS*LL. outd[base+e] has global float
    // index 1+base+e; base%4==0 so e≡3 (mod 4) gives 16B-aligned float4 stores.
    float* outd = out + 1;
    float* outm = out + 1 + (size_t)BS * LL;
    float accL = 0.0f;

    if (tid < 4) {                      // head e=0,1,2 and tail e=4623
        int e = (tid < 3) ? tid : (LL - 1);
        int i = e / LNUM;
        int j = e - i * LNUM;
        float2 mi2 = s_mm[i];
        float2 mj2 = s_mm[j];
        float diff = mi2.x - mj2.x;
        float mk   = mi2.y * mj2.y;
        float d    = s_rel[e] - diff;
        float ad   = fabsf(d);
        float c    = fminf(ad, 1.0f);
        float le   = c * (ad - 0.5f * c);
        outd[base + e] = diff;
        outm[base + e] = mk;
        accL += le * mk;
    }

    for (int g = tid; g < NGRP; g += NTHR) {
        int e0 = 3 + (g << 2);
        int i0 = e0 / LNUM;
        int j0 = e0 - i0 * LNUM;
        float dvv[4], mvv[4];
#pragma unroll
        for (int n = 0; n < 4; n++) {
            int jn = j0 + n;
            int wrap = (jn >= LNUM) ? 1 : 0;
            int in = i0 + wrap;
            jn -= LNUM * wrap;
            float2 mi2 = s_mm[in];
            float2 mj2 = s_mm[jn];
            float diff = mi2.x - mj2.x;
            float mk   = mi2.y * mj2.y;
            float d    = s_rel[e0 + n] - diff;
            float ad   = fabsf(d);
            float c    = fminf(ad, 1.0f);
            float le   = c * (ad - 0.5f * c);
            dvv[n] = diff;
            mvv[n] = mk;
            accL += le * mk;
        }
        *reinterpret_cast<float4*>(outd + base + e0) =
            make_float4(dvv[0], dvv[1], dvv[2], dvv[3]);
        *reinterpret_cast<float4*>(outm + base + e0) =
            make_float4(mvv[0], mvv[1], mvv[2], mvv[3]);
    }

    // ---- block reduce + global atomics + last-block finalize ----
    double dL = (double)accL;
#pragma unroll
    for (int o = 16; o > 0; o >>= 1)
        dL += __shfl_down_sync(FULLM, dL, o);
    if (lane == 0) redL[wid] = dL;
    __syncthreads();
    if (tid == 0) {
        double tL = 0.0;
#pragma unroll
        for (int w = 0; w < NWARP; w++) tL += redL[w];
        double cnt = (double)(s_cnt[0] + s_cnt[1] + s_cnt[2]);
        atomicAdd(&g_sumL, tL);
        atomicAdd(&g_sumM, cnt * cnt);      // sum_ij mi*mj == (sum m)^2
        __threadfence();
        unsigned n = atomicAdd(&g_done, 1u);
        s_last = (n == BS - 1);
    }
    __syncthreads();

    if (s_last && tid == 0) {
        __threadfence();
        double L = g_sumL, M = g_sumM;
        out[0] = (float)(L / (M + 1e-4));
        g_sumL = 0.0; g_sumM = 0.0; g_done = 0u;
    }
}

extern "C" void kernel_launch(void* const* d_in, const int* in_sizes, int n_in,
                              void* d_out, int out_size)
{
    const float* rel   = (const float*)d_in[0];   // [BS, L, L]
    const float* depth = (const float*)d_in[1];   // [BS, 1, IMG, IMG]
    const float* lm    = (const float*)d_in[2];   // [BS, L, 2]
    const float* sf    = (const float*)d_in[3];   // [BS, 2]
    const float* bbox  = (const float*)d_in[4];   // [BS, 4]
    float* out = (float*)d_out;                   // [loss | diff | mask]

    fused_kernel<<<BS, NTHR>>>(rel, depth, lm, sf, bbox, out);
}

// round 10
// speedup vs baseline: 1.4231x; 1.0530x over previous
#include <cuda_runtime.h>
#include <math.h>
#include <stdint.h>

#define BS    512
#define LNUM  68
#define IMG   224
#define RS    7
#define R2    49
#define LL    (LNUM * LNUM)     // 4624
#define NLM   (BS * LNUM)       // 34816
#define FULLM 0xFFFFFFFFu

#define K1_THREADS 128
#define K2_THREADS 512
#define K2_WARPS   16
#define NGRP  ((LL - 4) / 4)    // 1155 float4 store groups per batch

__device__ float    g_median[NLM];
__device__ double   g_sumL = 0.0;
__device__ double   g_sumM = 0.0;
__device__ unsigned g_done = 0u;

__device__ __forceinline__ uint32_t smem_u32(const void* p) {
    return (uint32_t)__cvta_generic_to_shared(p);
}

// linspace(-3.5,3.5,7)[k] / 224 * 2 — identical op order to the reference.
__device__ __forceinline__ float xval(int k) {
    float x = -3.5f + (float)k * (7.0f / 6.0f);
    if (k == RS - 1) x = 3.5f;
    return x / 224.0f * 2.0f;
}

// ---- K1: one THREAD per landmark; full register sort (no warp collectives,
// no launch_bounds reg cap -> v[49] lives in the register file).
__global__ __launch_bounds__(K1_THREADS) void k1_region_median(
    const float* __restrict__ depth,
    const float* __restrict__ lm,
    const float* __restrict__ sf,
    const float* __restrict__ bbox)
{
    int idx = blockIdx.x * K1_THREADS + threadIdx.x;
    if (idx >= NLM) return;
    int b = idx / LNUM;

    float sf0 = __ldg(sf + b * 2 + 0), sf1 = __ldg(sf + b * 2 + 1);
    float bx  = __ldg(bbox + b * 4 + 0), by = __ldg(bbox + b * 4 + 1);
    const float* dimg = depth + (size_t)b * IMG * IMG;

    float2 lxy = *reinterpret_cast<const float2*>(lm + (size_t)idx * 2);
    float fx = (lxy.x - bx) * sf0 / 224.0f * 2.0f - 1.0f;
    float fy = (lxy.y - by) * sf1 / 224.0f * 2.0f - 1.0f;

    // hoisted per-axis indices (exact reference arithmetic; rintf == jnp.round)
    int  coloff[RS];
    bool vx[RS];
#pragma unroll
    for (int q = 0; q < RS; q++) {
        float gx = fx + xval(q);
        float ix = ((gx + 1.0f) * 224.0f - 1.0f) * 0.5f;
        int xi = (int)rintf(ix);
        vx[q] = (xi >= 0) & (xi < IMG);
        coloff[q] = min(max(xi, 0), IMG - 1);
    }

    float v[R2];
    int   k = 0;
#pragma unroll
    for (int p = 0; p < RS; p++) {
        float gy = fy + xval(p);
        float iy = ((gy + 1.0f) * 224.0f - 1.0f) * 0.5f;
        int yi = (int)rintf(iy);
        bool vy = (yi >= 0) & (yi < IMG);
        int ro = min(max(yi, 0), IMG - 1) * IMG;
#pragma unroll
        for (int q = 0; q < RS; q++) {
            float val = __ldg(dimg + ro + coloff[q]);
            val = (vy & vx[q]) ? val : 0.0f;
            v[p * RS + q] = val;
            k += (val <= 1e-4f) ? 1 : 0;
        }
    }

    // Batcher odd-even merge sort, n=64 network pruned to 49 live slots
    // (skipped exchanges pair with implicit +INF -> no-ops). Compile-time
    // indices -> pure register sort on the ALU pipe.
#pragma unroll
    for (int p = 1; p < 64; p <<= 1) {
#pragma unroll
        for (int kk = p; kk >= 1; kk >>= 1) {
#pragma unroll
            for (int j = kk & (p - 1); j + kk < 64; j += 2 * kk) {
#pragma unroll
                for (int i = 0; i < kk; i++) {
                    if (i + j + kk < R2) {
                        if ((i + j) / (2 * p) == (i + j + kk) / (2 * p)) {
                            float a  = v[i + j];
                            float bb = v[i + j + kk];
                            v[i + j]      = fminf(a, bb);
                            v[i + j + kk] = fmaxf(a, bb);
                        }
                    }
                }
            }
        }
    }

    // median rank: mi = (clamp(k,1,48)+48)/2 in [24,48]
    int st = min(max(k, 1), R2 - 1);
    int mi = (st + R2 - 1) >> 1;
    float r = v[24];
#pragma unroll
    for (int i = 25; i < R2; i++) r = (mi >= i) ? v[i] : r;
    g_median[idx] = r;
}

// ---- K2: per-batch mom + mask + pairwise loss (TMA stage-in, float4 out) --
__global__ __launch_bounds__(K2_THREADS, 3) void k2_pairwise(
    const float* __restrict__ rel,
    float* __restrict__ out)
{
    __shared__ float  s_rel[LL];             // staged via cp.async.bulk
    __shared__ float  smed[LNUM];
    __shared__ float2 s_mm[LNUM];            // (med*500, mask)
    __shared__ float  s_mom;
    __shared__ int    s_cnt[3];
    __shared__ double redL[K2_WARPS];
    __shared__ bool   s_last;
    __shared__ __align__(8) unsigned long long s_mbar;

    int b    = blockIdx.x;
    int tid  = threadIdx.x;
    int wid  = tid >> 5;
    int lane = tid & 31;

    const size_t base = (size_t)b * LL;
    const float* relb = rel + base;

    // stage rel[batch] -> smem, overlapping the prologue
    uint32_t mb = smem_u32(&s_mbar);
    if (tid == 0) {
        asm volatile("mbarrier.init.shared.b64 [%0], 1;" :: "r"(mb) : "memory");
        asm volatile("fence.proxy.async.shared::cta;" ::: "memory");
        asm volatile("mbarrier.arrive.expect_tx.shared.b64 _, [%0], %1;"
                     :: "r"(mb), "r"((uint32_t)(LL * 4)) : "memory");
        asm volatile("cp.async.bulk.shared::cta.global.mbarrier::complete_tx::bytes "
                     "[%0], [%1], %2, [%3];"
                     :: "r"(smem_u32(s_rel)), "l"(relb),
                        "r"((uint32_t)(LL * 4)), "r"(mb) : "memory");
    }

    // prologue: load medians, lower median-of-medians (rank 33), mask, count
    float vraw = 0.0f;
    if (tid < LNUM) {
        vraw = g_median[b * LNUM + tid];
        smed[tid] = vraw;
    }
    __syncthreads();
    if (tid < LNUM) {
        int r = 0;
#pragma unroll 4
        for (int j = 0; j < LNUM; j++) {
            float w = smed[j];
            r += (w < vraw || (w == vraw && j < tid)) ? 1 : 0;  // stable rank
        }
        if (r == (LNUM - 1) / 2) s_mom = vraw;
    }
    __syncthreads();
    bool mbit = false;
    if (tid < LNUM) {
        mbit = fabsf(vraw - s_mom) < (90.0f / 500.0f);
        s_mm[tid] = make_float2(vraw * 500.0f, mbit ? 1.0f : 0.0f);
    }
    unsigned bal = __ballot_sync(FULLM, mbit);
    if (lane == 0 && wid < 3) s_cnt[wid] = __popc(bal);
    __syncthreads();

    // wait for staged rel (TRYWAIT fast path, normally complete by now)
    {
        uint32_t done;
        do {
            asm volatile(
                "{\n\t.reg .pred p;\n\t"
                "mbarrier.try_wait.parity.acquire.cta.shared::cta.b64 p, [%1], %2;\n\t"
                "selp.b32 %0, 1, 0, p;\n\t}"
                : "=r"(done) : "r"(mb), "r"(0u) : "memory");
        } while (!done);
    }

    // pairwise diff / mask / smooth-L1, float4 stores.
    // out[0]=loss, outd=out+1, outm=out+1+BS*LL. outd[base+e] has global float
    // index 1+base+e; base%4==0 so e≡3 (mod 4) gives 16B-aligned float4 stores.
    float* outd = out + 1;
    float* outm = out + 1 + (size_t)BS * LL;
    float accL = 0.0f;

    if (tid < 4) {                      // head e=0,1,2 and tail e=4623
        int e = (tid < 3) ? tid : (LL - 1);
        int i = e / LNUM;
        int j = e - i * LNUM;
        float2 mi2 = s_mm[i];
        float2 mj2 = s_mm[j];
        float diff = mi2.x - mj2.x;
        float mk   = mi2.y * mj2.y;
        float d    = s_rel[e] - diff;
        float ad   = fabsf(d);
        float c    = fminf(ad, 1.0f);
        float le   = c * (ad - 0.5f * c);
        outd[base + e] = diff;
        outm[base + e] = mk;
        accL += le * mk;
    }

    for (int g = tid; g < NGRP; g += K2_THREADS) {
        int e0 = 3 + (g << 2);
        int i0 = e0 / LNUM;
        int j0 = e0 - i0 * LNUM;
        float dvv[4], mvv[4];
#pragma unroll
        for (int n = 0; n < 4; n++) {
            int jn = j0 + n;
            int wrap = (jn >= LNUM) ? 1 : 0;
            int in = i0 + wrap;
            jn -= LNUM * wrap;
            float2 mi2 = s_mm[in];
            float2 mj2 = s_mm[jn];
            float diff = mi2.x - mj2.x;
            float mk   = mi2.y * mj2.y;
            float d    = s_rel[e0 + n] - diff;
            float ad   = fabsf(d);
            float c    = fminf(ad, 1.0f);
            float le   = c * (ad - 0.5f * c);
            dvv[n] = diff;
            mvv[n] = mk;
            accL += le * mk;
        }
        *reinterpret_cast<float4*>(outd + base + e0) =
            make_float4(dvv[0], dvv[1], dvv[2], dvv[3]);
        *reinterpret_cast<float4*>(outm + base + e0) =
            make_float4(mvv[0], mvv[1], mvv[2], mvv[3]);
    }

    // block reduce + global atomics + last-block finalize
    double dL = (double)accL;
#pragma unroll
    for (int o = 16; o > 0; o >>= 1)
        dL += __shfl_down_sync(FULLM, dL, o);
    if (lane == 0) redL[wid] = dL;
    __syncthreads();
    if (tid == 0) {
        double tL = 0.0;
#pragma unroll
        for (int w = 0; w < K2_WARPS; w++) tL += redL[w];
        double cnt = (double)(s_cnt[0] + s_cnt[1] + s_cnt[2]);
        atomicAdd(&g_sumL, tL);
        atomicAdd(&g_sumM, cnt * cnt);      // sum_ij mi*mj == (sum m)^2
        __threadfence();
        unsigned n = atomicAdd(&g_done, 1u);
        s_last = (n == BS - 1);
    }
    __syncthreads();

    if (s_last && tid == 0) {
        __threadfence();
        double L = g_sumL, M = g_sumM;
        out[0] = (float)(L / (M + 1e-4));
        g_sumL = 0.0; g_sumM = 0.0; g_done = 0u;
    }
}

extern "C" void kernel_launch(void* const* d_in, const int* in_sizes, int n_in,
                              void* d_out, int out_size)
{
    const float* rel   = (const float*)d_in[0];   // [BS, L, L]
    const float* depth = (const float*)d_in[1];   // [BS, 1, IMG, IMG]
    const float* lm    = (const float*)d_in[2];   // [BS, L, 2]
    const float* sf    = (const float*)d_in[3];   // [BS, 2]
    const float* bbox  = (const float*)d_in[4];   // [BS, 4]
    float* out = (float*)d_out;                   // [loss | diff | mask]

    k1_region_median<<<(NLM + K1_THREADS - 1) / K1_THREADS, K1_THREADS>>>(
        depth, lm, sf, bbox);
    k2_pairwise<<<BS, K2_THREADS>>>(rel, out);
}